// round 1
// baseline (speedup 1.0000x reference)
#include <cuda_runtime.h>
#include <cuda_bf16.h>
#include <math.h>

// Problem constants
#define BATCH 16
#define TT    1024   // T
#define DIN   384    // D_IN
#define H1C   1024
#define H2C   1024
#define KW    9

// ---------------- scratch (device globals; no allocation allowed) ------------
__device__ float g_w1T[DIN * H1C];            // [384,1024]
__device__ float g_w2T[H2C * DIN];            // [1024,384]
__device__ float g_inT[BATCH * DIN * TT];     // [16,384,1024]
__device__ float g_x  [BATCH * H1C * TT];     // mish output, channel-major
__device__ float g_y  [BATCH * H1C * TT];     // conv output * p_g
__device__ float g_z  [BATCH * H2C * TT];     // pointwise output
__device__ float g_invnd[BATCH * KW];
__device__ float g_invnp[BATCH * H2C];

// ---------------- helpers ----------------------------------------------------
__device__ __forceinline__ float mish_f(float v) {
    // softplus stable: max(v,0) + log1p(exp(-|v|))
    float sp = fmaxf(v, 0.f) + log1pf(expf(-fabsf(v)));
    return v * tanhf(sp);
}

// ---------------- transpose: in[rows,cols] -> out[cols,rows], batched --------
__global__ void transpose_kernel(const float* __restrict__ in, float* __restrict__ out,
                                 int rows, int cols, long long in_bs, long long out_bs) {
    __shared__ float tile[32][33];
    int b = blockIdx.z;
    const float* I = in + (long long)b * in_bs;
    float* O = out + (long long)b * out_bs;
    int r0 = blockIdx.y * 32, c0 = blockIdx.x * 32;
    int tx = threadIdx.x, ty = threadIdx.y;  // 32 x 8
#pragma unroll
    for (int i = ty; i < 32; i += 8) {
        int r = r0 + i, c = c0 + tx;
        tile[i][tx] = (r < rows && c < cols) ? I[(long long)r * cols + c] : 0.f;
    }
    __syncthreads();
#pragma unroll
    for (int i = ty; i < 32; i += 8) {
        int c = c0 + i, r = r0 + tx;
        if (c < cols && r < rows) O[(long long)c * rows + r] = tile[tx][i];
    }
}

// ---------------- norm of d_w over H1 per (b,k) ------------------------------
__global__ void dnorm_kernel(const float* __restrict__ d_w, float* __restrict__ invnd) {
    int b = blockIdx.x / KW, k = blockIdx.x % KW;
    float s = 0.f;
    for (int c = threadIdx.x; c < H1C; c += 128) {
        float v = d_w[((long long)b * H1C + c) * KW + k];
        s += v * v;
    }
#pragma unroll
    for (int o = 16; o > 0; o >>= 1) s += __shfl_xor_sync(0xffffffffu, s, o);
    __shared__ float ws[4];
    int lane = threadIdx.x & 31, wid = threadIdx.x >> 5;
    if (lane == 0) ws[wid] = s;
    __syncthreads();
    if (threadIdx.x == 0) {
        float t = ws[0] + ws[1] + ws[2] + ws[3];
        invnd[b * KW + k] = 1.f / fmaxf(sqrtf(t), 1e-12f);
    }
}

// ---------------- norm of p_w over H1 per (b,o) ------------------------------
__global__ void pnorm_kernel(const float* __restrict__ p_w, float* __restrict__ invnp) {
    int i = blockIdx.x * blockDim.x + threadIdx.x;  // B*H2 threads
    int b = i >> 10, o = i & 1023;
    const float* base = p_w + (long long)b * H1C * H2C + o;
    float s = 0.f;
#pragma unroll 8
    for (int c = 0; c < H1C; c++) {
        float v = base[(long long)c * H2C];
        s += v * v;
    }
    invnp[i] = 1.f / fmaxf(sqrtf(s), 1e-12f);
}

// ---------------- depthwise conv (K=9, same pad), fold d_b, *T, *p_g ---------
__global__ void dwconv_kernel(const float* __restrict__ d_w, const float* __restrict__ d_g,
                              const float* __restrict__ d_b, const float* __restrict__ p_g) {
    int bc = blockIdx.x;             // b*H1 + c
    int b = bc >> 10, c = bc & 1023;
    __shared__ float s[TT + 8];
    __shared__ float w[KW];
    const float* xr = g_x + (long long)bc * TT;
    int tid = threadIdx.x;           // 256
    for (int i = tid; i < TT + 8; i += 256) {
        int t = i - 4;
        s[i] = (t >= 0 && t < TT) ? xr[t] : 0.f;
    }
    if (tid < KW)
        w[tid] = d_w[(long long)bc * KW + tid] * g_invnd[b * KW + tid] * d_g[bc];
    __syncthreads();
    float bias = d_b[bc];
    float pg = p_g[bc];
    float* yr = g_y + (long long)bc * TT;
    for (int t = tid; t < TT; t += 256) {
        float a = 0.f;
#pragma unroll
        for (int k = 0; k < KW; k++) a = fmaf(s[t + k], w[k], a);
        yr[t] = (a * (float)TT + bias) * pg;
    }
}

// ---------------- generic TN SGEMM: C[m,n] = sum_k A[k,m]*B[k,n] -------------
// MODE 1: v = mish(acc + aux1[m])
// MODE 2: v = acc*aux1[m] + aux2[m]
// MODE 3: v = acc + aux1[n] + R[m*ldc+n]  (R uses C's batch stride)
template <int MODE>
__global__ void __launch_bounds__(256, 2)
gemm_tn_kernel(const float* __restrict__ A, long long sA,
               const float* __restrict__ B, long long sB,
               float* __restrict__ C, long long sC,
               int Kd, int lda, int ldb, int ldc,
               const float* __restrict__ aux1, int a1s,
               const float* __restrict__ aux2, int a2s,
               const float* __restrict__ R) {
    const int BM = 128, BN = 128, BK = 8;
    int b = blockIdx.z;
    const float* Ab = A + (long long)b * sA;
    const float* Bb = B + (long long)b * sB;
    float* Cb = C + (long long)b * sC;
    const float* Rb = (MODE == 3) ? R + (long long)b * sC : nullptr;
    const float* a1 = aux1 + (long long)b * a1s;
    const float* a2 = (MODE == 2) ? aux2 + (long long)b * a2s : nullptr;

    int m0 = blockIdx.y * BM, n0 = blockIdx.x * BN;
    __shared__ float As[BK][BM];
    __shared__ float Bs[BK][BN];
    int tid = threadIdx.x;
    int lk = tid >> 5;              // 0..7
    int lm = (tid & 31) << 2;       // 0..124 step 4
    int tx = tid & 15, ty = tid >> 4;
    int tm = ty * 8, tn = tx * 8;

    float acc[8][8];
#pragma unroll
    for (int i = 0; i < 8; i++)
#pragma unroll
        for (int j = 0; j < 8; j++) acc[i][j] = 0.f;

    for (int k0 = 0; k0 < Kd; k0 += BK) {
        *(float4*)&As[lk][lm] = *(const float4*)&Ab[(long long)(k0 + lk) * lda + m0 + lm];
        *(float4*)&Bs[lk][lm] = *(const float4*)&Bb[(long long)(k0 + lk) * ldb + n0 + lm];
        __syncthreads();
#pragma unroll
        for (int k = 0; k < BK; k++) {
            float ra[8], rb[8];
            *(float4*)&ra[0] = *(float4*)&As[k][tm];
            *(float4*)&ra[4] = *(float4*)&As[k][tm + 4];
            *(float4*)&rb[0] = *(float4*)&Bs[k][tn];
            *(float4*)&rb[4] = *(float4*)&Bs[k][tn + 4];
#pragma unroll
            for (int i = 0; i < 8; i++)
#pragma unroll
                for (int j = 0; j < 8; j++) acc[i][j] = fmaf(ra[i], rb[j], acc[i][j]);
        }
        __syncthreads();
    }

#pragma unroll
    for (int i = 0; i < 8; i++) {
        int m = m0 + tm + i;
        long long rowoff = (long long)m * ldc + n0 + tn;
        float vals[8];
        if (MODE == 1) {
            float bias = a1[m];
#pragma unroll
            for (int j = 0; j < 8; j++) vals[j] = mish_f(acc[i][j] + bias);
        } else if (MODE == 2) {
            float sc = a1[m], pb = a2[m];
#pragma unroll
            for (int j = 0; j < 8; j++) vals[j] = fmaf(acc[i][j], sc, pb);
        } else {
#pragma unroll
            for (int j = 0; j < 8; j++) vals[j] = acc[i][j] + a1[n0 + tn + j] + Rb[rowoff + j];
        }
        *(float4*)&Cb[rowoff]     = make_float4(vals[0], vals[1], vals[2], vals[3]);
        *(float4*)&Cb[rowoff + 4] = make_float4(vals[4], vals[5], vals[6], vals[7]);
    }
}

// ---------------- launch ------------------------------------------------------
extern "C" void kernel_launch(void* const* d_in, const int* in_sizes, int n_in,
                              void* d_out, int out_size) {
    const float* input = (const float*)d_in[0];
    const float* d_w   = (const float*)d_in[1];
    const float* d_g   = (const float*)d_in[2];
    const float* d_b   = (const float*)d_in[3];
    const float* p_w   = (const float*)d_in[4];
    const float* p_g   = (const float*)d_in[5];
    const float* p_b   = (const float*)d_in[6];
    const float* w1_w  = (const float*)d_in[7];
    const float* w1_b  = (const float*)d_in[8];
    const float* w2_w  = (const float*)d_in[9];
    const float* w2_b  = (const float*)d_in[10];
    float* out = (float*)d_out;
    (void)in_sizes; (void)n_in; (void)out_size;

    float *p_w1T, *p_w2T, *p_inT, *p_x, *p_y, *p_z, *p_invnd, *p_invnp;
    cudaGetSymbolAddress((void**)&p_w1T, g_w1T);
    cudaGetSymbolAddress((void**)&p_w2T, g_w2T);
    cudaGetSymbolAddress((void**)&p_inT, g_inT);
    cudaGetSymbolAddress((void**)&p_x, g_x);
    cudaGetSymbolAddress((void**)&p_y, g_y);
    cudaGetSymbolAddress((void**)&p_z, g_z);
    cudaGetSymbolAddress((void**)&p_invnd, g_invnd);
    cudaGetSymbolAddress((void**)&p_invnp, g_invnp);

    dim3 tb(32, 8);
    // w1 [H1,DIN] -> w1T [DIN,H1]
    transpose_kernel<<<dim3(DIN / 32, H1C / 32, 1), tb>>>(w1_w, p_w1T, H1C, DIN, 0, 0);
    // w2 [DIN,H2] -> w2T [H2,DIN]
    transpose_kernel<<<dim3(H2C / 32, DIN / 32, 1), tb>>>(w2_w, p_w2T, DIN, H2C, 0, 0);
    // input [B,T,DIN] -> inT [B,DIN,T]
    transpose_kernel<<<dim3(DIN / 32, TT / 32, BATCH), tb>>>(input, p_inT, TT, DIN,
                                                            (long long)TT * DIN,
                                                            (long long)DIN * TT);
    dnorm_kernel<<<BATCH * KW, 128>>>(d_w, p_invnd);
    pnorm_kernel<<<BATCH * H2C / 256, 256>>>(p_w, p_invnp);

    // GEMM1: x[b,c,t] = mish( sum_d w1T[d,c]*inT[b,d,t] + w1_b[c] )
    gemm_tn_kernel<1><<<dim3(TT / 128, H1C / 128, BATCH), 256>>>(
        p_w1T, 0, p_inT, (long long)DIN * TT, p_x, (long long)H1C * TT,
        DIN, H1C, TT, TT, w1_b, 0, nullptr, 0, nullptr);

    // depthwise conv -> y' (includes *T, +d_b, *p_g)
    dwconv_kernel<<<BATCH * H1C, 256>>>(d_w, d_g, d_b, p_g);

    // GEMM2: z[b,o,t] = invnp[b,o]*( sum_c p_w[b,c,o]*y'[b,c,t] ) + p_b[b,o]
    gemm_tn_kernel<2><<<dim3(TT / 128, H2C / 128, BATCH), 256>>>(
        p_w, (long long)H1C * H2C, p_y, (long long)H1C * TT, p_z, (long long)H2C * TT,
        H1C, H2C, TT, TT, p_invnp, H2C, p_b, H2C, nullptr);

    // GEMM3: out[b,t,d] = sum_o z[b,o,t]*w2T[o,d] + w2_b[d] + input[b,t,d]
    gemm_tn_kernel<3><<<dim3(DIN / 128, TT / 128, BATCH), 256>>>(
        p_z, (long long)H2C * TT, p_w2T, 0, out, (long long)TT * DIN,
        H2C, TT, DIN, DIN, w2_b, 0, nullptr, 0, input);
}

// round 4
// speedup vs baseline: 1.6685x; 1.6685x over previous
#include <cuda_runtime.h>
#include <cuda_bf16.h>
#include <stdint.h>
#include <math.h>

// Problem constants
#define BATCH 16
#define TT    1024
#define DIN   384
#define H1C   1024
#define H2C   1024
#define KW    9

// ---------------- scratch (device globals) -----------------------------------
// bf16 split arrays store [hi-block | lo-block] along k (row length 2*K).
__device__ __align__(128) __nv_bfloat16 g_ins[BATCH * TT * (2 * DIN)];     // input split  [b][t][768]
__device__ __align__(128) __nv_bfloat16 g_w1s[H1C * (2 * DIN)];            // w1 split     [c][768]
__device__ __align__(128) __nv_bfloat16 g_w2s[DIN * (2 * H2C)];            // w2 split     [d][2048]
__device__ __align__(128) __nv_bfloat16 g_pwT[BATCH * H2C * (2 * H1C)];    // p_w^T split  [b][o][2048]
__device__ __align__(128) __nv_bfloat16 g_y2 [BATCH * TT * (2 * H1C)];     // y split      [b][t][2048]
__device__ __align__(128) __nv_bfloat16 g_z2 [BATCH * TT * (2 * H2C)];     // z split      [b][t][2048]
__device__ __align__(128) float g_x[BATCH * TT * H1C];                     // mish out f32 [b][t][c]
__device__ float g_invnd[BATCH * KW];
__device__ float g_invnp[BATCH * H2C];

// ---------------- helpers ----------------------------------------------------
__device__ __forceinline__ float mish_f(float v) {
    float sp = fmaxf(v, 0.f) + log1pf(expf(-fabsf(v)));
    return v * tanhf(sp);
}

__device__ __forceinline__ unsigned smem_u32(const void* p) {
    unsigned a;
    asm("{ .reg .u64 t; cvta.to.shared.u64 t, %1; cvt.u32.u64 %0, t; }" : "=r"(a) : "l"(p));
    return a;
}

__device__ __forceinline__ void cp_async16(unsigned dst, const void* src) {
    asm volatile("cp.async.cg.shared.global [%0], [%1], 16;" :: "r"(dst), "l"(src));
}

__device__ __forceinline__ void ldsm_x4(unsigned* r, unsigned addr) {
    asm volatile("ldmatrix.sync.aligned.m8n8.x4.shared.b16 {%0,%1,%2,%3}, [%4];"
        : "=r"(r[0]), "=r"(r[1]), "=r"(r[2]), "=r"(r[3]) : "r"(addr));
}

__device__ __forceinline__ void mma16816(float* d, const unsigned* a, unsigned b0, unsigned b1) {
    asm volatile("mma.sync.aligned.m16n8k16.row.col.f32.bf16.bf16.f32 "
        "{%0,%1,%2,%3}, {%4,%5,%6,%7}, {%8,%9}, {%0,%1,%2,%3};"
        : "+f"(d[0]), "+f"(d[1]), "+f"(d[2]), "+f"(d[3])
        : "r"(a[0]), "r"(a[1]), "r"(a[2]), "r"(a[3]), "r"(b0), "r"(b1));
}

// ---------------- split: f32 [R][K] -> bf16 [R][hi(K)|lo(K)] -----------------
__global__ void split_kernel(const float* __restrict__ in, __nv_bfloat16* __restrict__ out,
                             int K, long long total) {
    long long i = (long long)blockIdx.x * blockDim.x + threadIdx.x;
    if (i >= total) return;
    int k = (int)(i % K);
    long long r = i / K;
    float v = in[i];
    __nv_bfloat16 h = __float2bfloat16(v);
    __nv_bfloat16 l = __float2bfloat16(v - __bfloat162float(h));
    out[r * (2LL * K) + k] = h;
    out[r * (2LL * K) + K + k] = l;
}

// ---------------- transpose+split p_w [b][c][o] -> [b][o][hi(c)|lo(c)] -------
__global__ void tsplit_kernel(const float* __restrict__ in, __nv_bfloat16* __restrict__ out) {
    __shared__ float tile[32][33];
    int b = blockIdx.z;
    int o0 = blockIdx.x * 32, c0 = blockIdx.y * 32;
    const float* I = in + (long long)b * H1C * H2C;
    __nv_bfloat16* O = out + (long long)b * H2C * (2 * H1C);
    int tx = threadIdx.x, ty = threadIdx.y;  // 32 x 8
#pragma unroll
    for (int i = ty; i < 32; i += 8)
        tile[i][tx] = I[(long long)(c0 + i) * H2C + o0 + tx];
    __syncthreads();
#pragma unroll
    for (int i = ty; i < 32; i += 8) {
        int o = o0 + i, c = c0 + tx;
        float v = tile[tx][i];
        __nv_bfloat16 h = __float2bfloat16(v);
        __nv_bfloat16 l = __float2bfloat16(v - __bfloat162float(h));
        O[(long long)o * (2 * H1C) + c] = h;
        O[(long long)o * (2 * H1C) + H1C + c] = l;
    }
}

// ---------------- d_w norm over H1 per (b,k) ---------------------------------
__global__ void dnorm_kernel(const float* __restrict__ d_w, float* __restrict__ invnd) {
    int b = blockIdx.x / KW, k = blockIdx.x % KW;
    float s = 0.f;
    for (int c = threadIdx.x; c < H1C; c += 128) {
        float v = d_w[((long long)b * H1C + c) * KW + k];
        s += v * v;
    }
#pragma unroll
    for (int o = 16; o > 0; o >>= 1) s += __shfl_xor_sync(0xffffffffu, s, o);
    __shared__ float ws[4];
    int lane = threadIdx.x & 31, wid = threadIdx.x >> 5;
    if (lane == 0) ws[wid] = s;
    __syncthreads();
    if (threadIdx.x == 0) {
        float t = ws[0] + ws[1] + ws[2] + ws[3];
        invnd[b * KW + k] = 1.f / fmaxf(sqrtf(t), 1e-12f);
    }
}

// ---------------- p_w norm over H1 per (b,o) ---------------------------------
__global__ void pnorm_kernel(const float* __restrict__ p_w, float* __restrict__ invnp) {
    int i = blockIdx.x * blockDim.x + threadIdx.x;
    int b = i >> 10, o = i & 1023;
    const float* base = p_w + (long long)b * H1C * H2C + o;
    float s = 0.f;
#pragma unroll 8
    for (int c = 0; c < H1C; c++) {
        float v = base[(long long)c * H2C];
        s += v * v;
    }
    invnp[i] = 1.f / fmaxf(sqrtf(s), 1e-12f);
}

// ---------------- depthwise conv along t; x[b][t][c] -> y2 split -------------
__global__ void dwconv_kernel(const float* __restrict__ x, __nv_bfloat16* __restrict__ y2,
                              const float* __restrict__ d_w, const float* __restrict__ d_g,
                              const float* __restrict__ d_b, const float* __restrict__ p_g,
                              const float* __restrict__ invnd) {
    int b = blockIdx.z;
    int c0 = blockIdx.x * 128;
    int t0 = blockIdx.y * 64;
    __shared__ float xs[72][128];
    __shared__ float ws[KW][128];
    __shared__ float sdb[128], spg[128];
    int tid = threadIdx.x;  // 256
    const float* xb = x + (long long)b * TT * H1C;
    for (int i = tid; i < 72 * 128; i += 256) {
        int r = i >> 7, c = i & 127;
        int t = t0 - 4 + r;
        xs[r][c] = (t >= 0 && t < TT) ? xb[(long long)t * H1C + c0 + c] : 0.f;
    }
    if (tid < 128) {
        int c = c0 + tid;
        float g = d_g[b * H1C + c];
#pragma unroll
        for (int k = 0; k < KW; k++)
            ws[k][tid] = d_w[((long long)b * H1C + c) * KW + k] * invnd[b * KW + k] * g;
        sdb[tid] = d_b[b * H1C + c];
        spg[tid] = p_g[b * H1C + c];
    }
    __syncthreads();
    int tx = tid & 127, ty = tid >> 7;
    float w9[KW];
#pragma unroll
    for (int k = 0; k < KW; k++) w9[k] = ws[k][tx];
    float db = sdb[tx], pg = spg[tx];
    __nv_bfloat16* yb = y2 + (long long)b * TT * (2 * H1C);
#pragma unroll 4
    for (int q = 0; q < 32; q++) {
        int tt = ty * 32 + q;
        float a = 0.f;
#pragma unroll
        for (int k = 0; k < KW; k++) a = fmaf(xs[tt + k][tx], w9[k], a);
        float v = (a * (float)TT + db) * pg;
        __nv_bfloat16 h = __float2bfloat16(v);
        __nv_bfloat16 l = __float2bfloat16(v - __bfloat162float(h));
        long long ro = (long long)(t0 + tt) * (2 * H1C);
        yb[ro + c0 + tx] = h;
        yb[ro + H1C + c0 + tx] = l;
    }
}

// ---------------- mma.sync bf16 GEMM: D[m,n] = sum_k A[m,k]*B[n,k] -----------
// 3-term split: segments (Ahi,Bhi), (Alo,Bhi), (Ahi,Blo).
// MODE 1: C f32 = mish(acc + aux1[n])
// MODE 2: C bf16-split = acc*aux1[b,n] + aux2[b,n]
// MODE 3: C f32 = acc + aux1[n] + R[b][m][n]
#define PITCH 80  // bytes per 32-bf16 smem row (64B data + 16B pad)
template <int MODE>
__global__ void __launch_bounds__(256)
gemm_mma(const __nv_bfloat16* __restrict__ A, long long sA,
         const __nv_bfloat16* __restrict__ B, long long sB,
         void* __restrict__ Cv, long long sC,
         int Ks, int ldc,
         const float* __restrict__ aux1, int a1s,
         const float* __restrict__ aux2, int a2s,
         const float* __restrict__ R) {
    // [stage][op][128 rows * 80B]
    __shared__ __align__(16) unsigned char sm[2][2][128 * PITCH];

    const int tid = threadIdx.x;
    const int wid = tid >> 5, lane = tid & 31;
    const int wm = wid & 1, wn = wid >> 1;   // 2 x 4 warp grid
    const int b = blockIdx.z;
    const int m0 = blockIdx.y * 128, n0 = blockIdx.x * 128;

    const char* Ab = (const char*)(A + (long long)b * sA);
    const char* Bb = (const char*)(B + (long long)b * sB);
    const long long rowb = (long long)Ks * 4;   // row = 2*Ks bf16

    // cp.async geometry: thread t loads row t/2, 2 chunks of 16B at (t&1)*32
    const int lrow = tid >> 1;
    const int lcB = (tid & 1) * 32;
    const char* Agp = Ab + (long long)(m0 + lrow) * rowb + lcB;
    const char* Bgp = Bb + (long long)(n0 + lrow) * rowb + lcB;
    const unsigned AsD = smem_u32(&sm[0][0][0]) + lrow * PITCH + lcB;
    const unsigned BsD = smem_u32(&sm[0][1][0]) + lrow * PITCH + lcB;
    const unsigned stageStride = 2 * 128 * PITCH;

    const int kcPerSeg = Ks >> 5;
    const int nch = 3 * kcPerSeg;

    float acc[4][4][4];
#pragma unroll
    for (int i = 0; i < 4; i++)
#pragma unroll
        for (int j = 0; j < 4; j++)
#pragma unroll
            for (int r = 0; r < 4; r++) acc[i][j][r] = 0.f;

    // ldmatrix lane offsets
    const unsigned aLane = (unsigned)((lane & 15) * PITCH + (lane >> 4) * 16);
    const unsigned bLane = (unsigned)(((lane & 8) + (lane & 7)) * PITCH + (lane >> 4) * 16);
    const unsigned baseA0 = smem_u32(&sm[0][0][0]) + (unsigned)(wm * 64 * PITCH);
    const unsigned baseB0 = smem_u32(&sm[0][1][0]) + (unsigned)(wn * 32 * PITCH);

#define ISSUE(ic) do { \
    int _seg = (ic) / kcPerSeg, _kk = (ic) - _seg * kcPerSeg; \
    int _ao = ((_seg == 1) ? Ks * 2 : 0) + _kk * 64; \
    int _bo = ((_seg == 2) ? Ks * 2 : 0) + _kk * 64; \
    unsigned _st = ((ic) & 1) * stageStride; \
    cp_async16(AsD + _st, Agp + _ao); \
    cp_async16(AsD + _st + 16, Agp + _ao + 16); \
    cp_async16(BsD + _st, Bgp + _bo); \
    cp_async16(BsD + _st + 16, Bgp + _bo + 16); \
    asm volatile("cp.async.commit_group;"); \
} while (0)

    ISSUE(0);
    if (nch > 1) ISSUE(1);

    for (int ic = 0; ic < nch; ic++) {
        if (ic + 1 < nch)
            asm volatile("cp.async.wait_group 1;");
        else
            asm volatile("cp.async.wait_group 0;");
        __syncthreads();

        unsigned st = (unsigned)(ic & 1) * stageStride;
        unsigned bA = baseA0 + st, bB = baseB0 + st;
#pragma unroll
        for (int ks = 0; ks < 2; ks++) {
            unsigned afr[4][4];
#pragma unroll
            for (int mi = 0; mi < 4; mi++)
                ldsm_x4(afr[mi], bA + (unsigned)(mi * 16 * PITCH) + (unsigned)(ks * 32) + aLane);
            unsigned bfr[4][2];
#pragma unroll
            for (int nj = 0; nj < 2; nj++) {
                unsigned r[4];
                ldsm_x4(r, bB + (unsigned)(nj * 16 * PITCH) + (unsigned)(ks * 32) + bLane);
                bfr[2 * nj][0] = r[0]; bfr[2 * nj][1] = r[2];
                bfr[2 * nj + 1][0] = r[1]; bfr[2 * nj + 1][1] = r[3];
            }
#pragma unroll
            for (int mi = 0; mi < 4; mi++)
#pragma unroll
                for (int ni = 0; ni < 4; ni++)
                    mma16816(acc[mi][ni], afr[mi], bfr[ni][0], bfr[ni][1]);
        }
        __syncthreads();
        if (ic + 2 < nch) ISSUE(ic + 2);
    }
#undef ISSUE

    // epilogue: c-frag thread mapping: rows quad, quad+8; cols 2*(lane&3)+{0,1}
    const int quad = lane >> 2;
    const int col2 = (lane & 3) * 2;
#pragma unroll
    for (int mi = 0; mi < 4; mi++) {
#pragma unroll
        for (int half = 0; half < 2; half++) {
            int m = m0 + wm * 64 + mi * 16 + quad + half * 8;
#pragma unroll
            for (int ni = 0; ni < 4; ni++) {
                int n = n0 + wn * 32 + ni * 8 + col2;
                float v0 = acc[mi][ni][2 * half];
                float v1 = acc[mi][ni][2 * half + 1];
                if (MODE == 1) {
                    v0 = mish_f(v0 + aux1[n]);
                    v1 = mish_f(v1 + aux1[n + 1]);
                    float* C = (float*)Cv + (long long)b * sC + (long long)m * ldc + n;
                    *(float2*)C = make_float2(v0, v1);
                } else if (MODE == 2) {
                    v0 = v0 * aux1[b * a1s + n] + aux2[b * a2s + n];
                    v1 = v1 * aux1[b * a1s + n + 1] + aux2[b * a2s + n + 1];
                    __nv_bfloat16 h0 = __float2bfloat16(v0);
                    __nv_bfloat16 l0 = __float2bfloat16(v0 - __bfloat162float(h0));
                    __nv_bfloat16 h1 = __float2bfloat16(v1);
                    __nv_bfloat16 l1 = __float2bfloat16(v1 - __bfloat162float(h1));
                    __nv_bfloat16* C = (__nv_bfloat16*)Cv + (long long)b * sC + (long long)m * (2 * H2C);
                    *(__nv_bfloat162*)(C + n) = __nv_bfloat162(h0, h1);
                    *(__nv_bfloat162*)(C + H2C + n) = __nv_bfloat162(l0, l1);
                } else {
                    long long off = (long long)b * sC + (long long)m * ldc + n;
                    v0 = v0 + aux1[n] + R[off];
                    v1 = v1 + aux1[n + 1] + R[off + 1];
                    *(float2*)((float*)Cv + off) = make_float2(v0, v1);
                }
            }
        }
    }
}

// ---------------- launch ------------------------------------------------------
extern "C" void kernel_launch(void* const* d_in, const int* in_sizes, int n_in,
                              void* d_out, int out_size) {
    const float* input = (const float*)d_in[0];
    const float* d_w   = (const float*)d_in[1];
    const float* d_g   = (const float*)d_in[2];
    const float* d_b   = (const float*)d_in[3];
    const float* p_w   = (const float*)d_in[4];
    const float* p_g   = (const float*)d_in[5];
    const float* p_b   = (const float*)d_in[6];
    const float* w1_w  = (const float*)d_in[7];
    const float* w1_b  = (const float*)d_in[8];
    const float* w2_w  = (const float*)d_in[9];
    const float* w2_b  = (const float*)d_in[10];
    float* out = (float*)d_out;
    (void)in_sizes; (void)n_in; (void)out_size;

    __nv_bfloat16 *p_ins, *p_w1s, *p_w2s, *p_pwT, *p_y2, *p_z2;
    float *p_x, *p_invnd, *p_invnp;
    cudaGetSymbolAddress((void**)&p_ins, g_ins);
    cudaGetSymbolAddress((void**)&p_w1s, g_w1s);
    cudaGetSymbolAddress((void**)&p_w2s, g_w2s);
    cudaGetSymbolAddress((void**)&p_pwT, g_pwT);
    cudaGetSymbolAddress((void**)&p_y2, g_y2);
    cudaGetSymbolAddress((void**)&p_z2, g_z2);
    cudaGetSymbolAddress((void**)&p_x, g_x);
    cudaGetSymbolAddress((void**)&p_invnd, g_invnd);
    cudaGetSymbolAddress((void**)&p_invnp, g_invnp);

    // operand preparation
    {
        long long t1 = (long long)H1C * DIN;
        split_kernel<<<(unsigned)((t1 + 255) / 256), 256>>>(w1_w, p_w1s, DIN, t1);
        long long t2 = (long long)BATCH * TT * DIN;
        split_kernel<<<(unsigned)((t2 + 255) / 256), 256>>>(input, p_ins, DIN, t2);
        long long t3 = (long long)DIN * H2C;
        split_kernel<<<(unsigned)((t3 + 255) / 256), 256>>>(w2_w, p_w2s, H2C, t3);
    }
    tsplit_kernel<<<dim3(H2C / 32, H1C / 32, BATCH), dim3(32, 8)>>>(p_w, p_pwT);
    dnorm_kernel<<<BATCH * KW, 128>>>(d_w, p_invnd);
    pnorm_kernel<<<BATCH * H2C / 256, 256>>>(p_w, p_invnp);

    // GEMM1: x[b][t][c] = mish( sum_d input[t,d]*w1[c,d] + w1_b[c] )
    gemm_mma<1><<<dim3(H1C / 128, TT / 128, BATCH), 256>>>(
        p_ins, (long long)TT * 2 * DIN, p_w1s, 0,
        (void*)p_x, (long long)TT * H1C, DIN, H1C,
        w1_b, 0, nullptr, 0, nullptr);

    // depthwise conv -> y2 split (includes *T, +d_b, *p_g)
    dwconv_kernel<<<dim3(H1C / 128, TT / 64, BATCH), 256>>>(
        p_x, p_y2, d_w, d_g, d_b, p_g, p_invnd);

    // GEMM2: z[b][t][o] = invnp[b,o]*( sum_c y[t,c]*pwT[o,c] ) + p_b[b,o]
    gemm_mma<2><<<dim3(H2C / 128, TT / 128, BATCH), 256>>>(
        p_y2, (long long)TT * 2 * H1C, p_pwT, (long long)H2C * 2 * H1C,
        (void*)p_z2, (long long)TT * 2 * H2C, H1C, 0,
        p_invnp, H2C, p_b, H2C, nullptr);

    // GEMM3: out[b][t][d] = sum_o z[t,o]*w2[d,o] + w2_b[d] + input[b][t][d]
    gemm_mma<3><<<dim3(DIN / 128, TT / 128, BATCH), 256>>>(
        p_z2, (long long)TT * 2 * H2C, p_w2s, 0,
        (void*)out, (long long)TT * DIN, H2C, DIN,
        w2_b, 0, nullptr, 0, input);
}

// round 5
// speedup vs baseline: 4.2186x; 2.5283x over previous
#include <cuda_runtime.h>
#include <cuda_fp16.h>
#include <stdint.h>
#include <math.h>

// Problem constants
#define BATCH 16
#define TT    1024
#define DIN   384
#define H1C   1024
#define H2C   1024
#define KW    9

// ---------------- scratch (device globals) -----------------------------------
__device__ __align__(128) __half g_inh[BATCH * TT * DIN];     // fp16 input   [b][t][384]
__device__ __align__(128) __half g_w1h[H1C * DIN];            // fp16 w1      [c][384]
__device__ __align__(128) __half g_w2h[DIN * H2C];            // fp16 w2      [d][1024]
__device__ __align__(128) __half g_pwT[BATCH * H2C * H1C];    // fp16 p_w^T   [b][o][1024]
__device__ __align__(128) __half g_xh [BATCH * TT * H1C];     // mish out     [b][t][c]
__device__ __align__(128) __half g_yh [BATCH * TT * H1C];     // conv out     [b][t][c]
__device__ __align__(128) __half g_zh [BATCH * TT * H2C];     // pointwise    [b][t][o]
__device__ float g_invnd[BATCH * KW];
__device__ float g_invnp[BATCH * H2C];

// ---------------- helpers ----------------------------------------------------
__device__ __forceinline__ float mish_f(float v) {
    float sp = fmaxf(v, 0.f) + log1pf(expf(-fabsf(v)));
    return v * tanhf(sp);
}

__device__ __forceinline__ unsigned smem_u32(const void* p) {
    unsigned a;
    asm("{ .reg .u64 t; cvta.to.shared.u64 t, %1; cvt.u32.u64 %0, t; }" : "=r"(a) : "l"(p));
    return a;
}

__device__ __forceinline__ void cp_async16(unsigned dst, const void* src) {
    asm volatile("cp.async.cg.shared.global [%0], [%1], 16;" :: "r"(dst), "l"(src));
}

__device__ __forceinline__ void ldsm_x4(unsigned* r, unsigned addr) {
    asm volatile("ldmatrix.sync.aligned.m8n8.x4.shared.b16 {%0,%1,%2,%3}, [%4];"
        : "=r"(r[0]), "=r"(r[1]), "=r"(r[2]), "=r"(r[3]) : "r"(addr));
}

__device__ __forceinline__ void mma16816(float* d, const unsigned* a, unsigned b0, unsigned b1) {
    asm volatile("mma.sync.aligned.m16n8k16.row.col.f32.f16.f16.f32 "
        "{%0,%1,%2,%3}, {%4,%5,%6,%7}, {%8,%9}, {%0,%1,%2,%3};"
        : "+f"(d[0]), "+f"(d[1]), "+f"(d[2]), "+f"(d[3])
        : "r"(a[0]), "r"(a[1]), "r"(a[2]), "r"(a[3]), "r"(b0), "r"(b1));
}

// ---------------- cvt: f32 -> f16, contiguous (total % 4 == 0) ---------------
__global__ void cvt_kernel(const float4* __restrict__ in, uint2* __restrict__ out,
                           long long total4) {
    long long i = (long long)blockIdx.x * blockDim.x + threadIdx.x;
    if (i >= total4) return;
    float4 v = in[i];
    __half2 a = __floats2half2_rn(v.x, v.y);
    __half2 b = __floats2half2_rn(v.z, v.w);
    out[i] = make_uint2(*(unsigned*)&a, *(unsigned*)&b);
}

// ---------------- transpose p_w [b][c][o] -> fp16 [b][o][c] ------------------
__global__ void tsplit_kernel(const float* __restrict__ in, __half* __restrict__ out) {
    __shared__ float tile[32][33];
    int b = blockIdx.z;
    int o0 = blockIdx.x * 32, c0 = blockIdx.y * 32;
    const float* I = in + (long long)b * H1C * H2C;
    __half* O = out + (long long)b * H2C * H1C;
    int tx = threadIdx.x, ty = threadIdx.y;  // 32 x 8
#pragma unroll
    for (int i = ty; i < 32; i += 8)
        tile[i][tx] = I[(long long)(c0 + i) * H2C + o0 + tx];
    __syncthreads();
#pragma unroll
    for (int i = ty; i < 32; i += 8)
        O[(long long)(o0 + i) * H1C + c0 + tx] = __float2half(tile[tx][i]);
}

// ---------------- d_w norm over H1 per (b,k) ---------------------------------
__global__ void dnorm_kernel(const float* __restrict__ d_w, float* __restrict__ invnd) {
    int b = blockIdx.x / KW, k = blockIdx.x % KW;
    float s = 0.f;
    for (int c = threadIdx.x; c < H1C; c += 128) {
        float v = d_w[((long long)b * H1C + c) * KW + k];
        s += v * v;
    }
#pragma unroll
    for (int o = 16; o > 0; o >>= 1) s += __shfl_xor_sync(0xffffffffu, s, o);
    __shared__ float ws[4];
    int lane = threadIdx.x & 31, wid = threadIdx.x >> 5;
    if (lane == 0) ws[wid] = s;
    __syncthreads();
    if (threadIdx.x == 0) {
        float t = ws[0] + ws[1] + ws[2] + ws[3];
        invnd[b * KW + k] = 1.f / fmaxf(sqrtf(t), 1e-12f);
    }
}

// ---------------- p_w norm over H1 per (b,o), from transposed fp16 -----------
__global__ void pnorm_kernel(const __half* __restrict__ pwT, float* __restrict__ invnp) {
    int row = blockIdx.x * 8 + (threadIdx.x >> 5);  // warp per (b,o) row
    int lane = threadIdx.x & 31;
    const __half2* p = (const __half2*)(pwT + (long long)row * H1C);
    float s = 0.f;
#pragma unroll 4
    for (int j = lane; j < H1C / 2; j += 32) {
        float2 v = __half22float2(p[j]);
        s += v.x * v.x + v.y * v.y;
    }
#pragma unroll
    for (int o = 16; o > 0; o >>= 1) s += __shfl_xor_sync(0xffffffffu, s, o);
    if (lane == 0) invnp[row] = 1.f / fmaxf(sqrtf(s), 1e-12f);
}

// ---------------- depthwise conv along t; x fp16 -> y fp16 -------------------
__global__ void dwconv_kernel(const __half* __restrict__ x, __half* __restrict__ y,
                              const float* __restrict__ d_w, const float* __restrict__ d_g,
                              const float* __restrict__ d_b, const float* __restrict__ p_g,
                              const float* __restrict__ invnd) {
    int b = blockIdx.z;
    int c0 = blockIdx.x * 128;
    int t0 = blockIdx.y * 64;
    __shared__ float xs[72][128];
    __shared__ float ws[KW][128];
    __shared__ float sdb[128], spg[128];
    int tid = threadIdx.x;  // 256
    const __half* xb = x + (long long)b * TT * H1C;
    for (int i = tid; i < 72 * 64; i += 256) {
        int r = i >> 6, c2 = i & 63;
        int t = t0 - 4 + r;
        float2 v = make_float2(0.f, 0.f);
        if (t >= 0 && t < TT)
            v = __half22float2(*(const __half2*)(xb + (long long)t * H1C + c0 + 2 * c2));
        xs[r][2 * c2] = v.x;
        xs[r][2 * c2 + 1] = v.y;
    }
    if (tid < 128) {
        int c = c0 + tid;
        float g = d_g[b * H1C + c];
#pragma unroll
        for (int k = 0; k < KW; k++)
            ws[k][tid] = d_w[((long long)b * H1C + c) * KW + k] * invnd[b * KW + k] * g;
        sdb[tid] = d_b[b * H1C + c];
        spg[tid] = p_g[b * H1C + c];
    }
    __syncthreads();
    int tx = tid & 127, ty = tid >> 7;
    float w9[KW];
#pragma unroll
    for (int k = 0; k < KW; k++) w9[k] = ws[k][tx];
    float db = sdb[tx], pg = spg[tx];
    __half* yb = y + (long long)b * TT * H1C;
#pragma unroll 4
    for (int q = 0; q < 32; q++) {
        int tt = ty * 32 + q;
        float a = 0.f;
#pragma unroll
        for (int k = 0; k < KW; k++) a = fmaf(xs[tt + k][tx], w9[k], a);
        float v = (a * (float)TT + db) * pg;
        yb[(long long)(t0 + tt) * H1C + c0 + tx] = __float2half(v);
    }
}

// ---------------- mma.sync fp16 GEMM: D[m,n] = sum_k A[m,k]*B[n,k] -----------
// MODE 1: C fp16 = mish(acc + aux1[n])
// MODE 2: C fp16 = acc*aux1[b,n] + aux2[b,n]
// MODE 3: C f32 = acc + aux1[n] + R[b][m][n]
#define PITCH 80  // bytes per 32-half smem row (64B data + 16B pad)
template <int MODE>
__global__ void __launch_bounds__(256)
gemm_mma(const __half* __restrict__ A, long long sA,
         const __half* __restrict__ B, long long sB,
         void* __restrict__ Cv, long long sC,
         int Ks, int ldc,
         const float* __restrict__ aux1, int a1s,
         const float* __restrict__ aux2, int a2s,
         const float* __restrict__ R) {
    // [stage][op][128 rows * 80B]
    __shared__ __align__(16) unsigned char sm[2][2][128 * PITCH];

    const int tid = threadIdx.x;
    const int wid = tid >> 5, lane = tid & 31;
    const int wm = wid & 1, wn = wid >> 1;   // 2 x 4 warp grid
    const int b = blockIdx.z;
    const int m0 = blockIdx.y * 128, n0 = blockIdx.x * 128;

    const char* Ab = (const char*)(A + (long long)b * sA);
    const char* Bb = (const char*)(B + (long long)b * sB);
    const long long rowb = (long long)Ks * 2;   // fp16 row bytes

    // cp.async geometry: thread t loads row t/2, 32B at (t&1)*32
    const int lrow = tid >> 1;
    const int lcB = (tid & 1) * 32;
    const char* Agp = Ab + (long long)(m0 + lrow) * rowb + lcB;
    const char* Bgp = Bb + (long long)(n0 + lrow) * rowb + lcB;
    const unsigned AsD = smem_u32(&sm[0][0][0]) + lrow * PITCH + lcB;
    const unsigned BsD = smem_u32(&sm[0][1][0]) + lrow * PITCH + lcB;
    const unsigned stageStride = 2 * 128 * PITCH;

    const int nch = Ks >> 5;

    float acc[4][4][4];
#pragma unroll
    for (int i = 0; i < 4; i++)
#pragma unroll
        for (int j = 0; j < 4; j++)
#pragma unroll
            for (int r = 0; r < 4; r++) acc[i][j][r] = 0.f;

    // ldmatrix lane offsets
    const unsigned aLane = (unsigned)((lane & 15) * PITCH + (lane >> 4) * 16);
    const unsigned bLane = (unsigned)(((lane & 8) + (lane & 7)) * PITCH + (lane >> 4) * 16);
    const unsigned baseA0 = smem_u32(&sm[0][0][0]) + (unsigned)(wm * 64 * PITCH);
    const unsigned baseB0 = smem_u32(&sm[0][1][0]) + (unsigned)(wn * 32 * PITCH);

#define ISSUE(ic) do { \
    int _o = (ic) * 64; \
    unsigned _st = ((ic) & 1) * stageStride; \
    cp_async16(AsD + _st, Agp + _o); \
    cp_async16(AsD + _st + 16, Agp + _o + 16); \
    cp_async16(BsD + _st, Bgp + _o); \
    cp_async16(BsD + _st + 16, Bgp + _o + 16); \
    asm volatile("cp.async.commit_group;"); \
} while (0)

    ISSUE(0);
    if (nch > 1) ISSUE(1);

    for (int ic = 0; ic < nch; ic++) {
        if (ic + 1 < nch)
            asm volatile("cp.async.wait_group 1;");
        else
            asm volatile("cp.async.wait_group 0;");
        __syncthreads();

        unsigned st = (unsigned)(ic & 1) * stageStride;
        unsigned bA = baseA0 + st, bB = baseB0 + st;
#pragma unroll
        for (int ks = 0; ks < 2; ks++) {
            unsigned afr[4][4];
#pragma unroll
            for (int mi = 0; mi < 4; mi++)
                ldsm_x4(afr[mi], bA + (unsigned)(mi * 16 * PITCH) + (unsigned)(ks * 32) + aLane);
            unsigned bfr[4][2];
#pragma unroll
            for (int nj = 0; nj < 2; nj++) {
                unsigned r[4];
                ldsm_x4(r, bB + (unsigned)(nj * 16 * PITCH) + (unsigned)(ks * 32) + bLane);
                bfr[2 * nj][0] = r[0]; bfr[2 * nj][1] = r[2];
                bfr[2 * nj + 1][0] = r[1]; bfr[2 * nj + 1][1] = r[3];
            }
#pragma unroll
            for (int mi = 0; mi < 4; mi++)
#pragma unroll
                for (int ni = 0; ni < 4; ni++)
                    mma16816(acc[mi][ni], afr[mi], bfr[ni][0], bfr[ni][1]);
        }
        __syncthreads();
        if (ic + 2 < nch) ISSUE(ic + 2);
    }
#undef ISSUE

    // epilogue: rows quad, quad+8; cols 2*(lane&3)+{0,1}
    const int quad = lane >> 2;
    const int col2 = (lane & 3) * 2;
#pragma unroll
    for (int mi = 0; mi < 4; mi++) {
#pragma unroll
        for (int half = 0; half < 2; half++) {
            int m = m0 + wm * 64 + mi * 16 + quad + half * 8;
#pragma unroll
            for (int ni = 0; ni < 4; ni++) {
                int n = n0 + wn * 32 + ni * 8 + col2;
                float v0 = acc[mi][ni][2 * half];
                float v1 = acc[mi][ni][2 * half + 1];
                if (MODE == 1) {
                    v0 = mish_f(v0 + aux1[n]);
                    v1 = mish_f(v1 + aux1[n + 1]);
                    __half* C = (__half*)Cv + (long long)b * sC + (long long)m * ldc + n;
                    *(__half2*)C = __floats2half2_rn(v0, v1);
                } else if (MODE == 2) {
                    v0 = v0 * aux1[b * a1s + n] + aux2[b * a2s + n];
                    v1 = v1 * aux1[b * a1s + n + 1] + aux2[b * a2s + n + 1];
                    __half* C = (__half*)Cv + (long long)b * sC + (long long)m * ldc + n;
                    *(__half2*)C = __floats2half2_rn(v0, v1);
                } else {
                    long long off = (long long)b * sC + (long long)m * ldc + n;
                    v0 = v0 + aux1[n] + R[off];
                    v1 = v1 + aux1[n + 1] + R[off + 1];
                    *(float2*)((float*)Cv + off) = make_float2(v0, v1);
                }
            }
        }
    }
}

// ---------------- launch ------------------------------------------------------
extern "C" void kernel_launch(void* const* d_in, const int* in_sizes, int n_in,
                              void* d_out, int out_size) {
    const float* input = (const float*)d_in[0];
    const float* d_w   = (const float*)d_in[1];
    const float* d_g   = (const float*)d_in[2];
    const float* d_b   = (const float*)d_in[3];
    const float* p_w   = (const float*)d_in[4];
    const float* p_g   = (const float*)d_in[5];
    const float* p_b   = (const float*)d_in[6];
    const float* w1_w  = (const float*)d_in[7];
    const float* w1_b  = (const float*)d_in[8];
    const float* w2_w  = (const float*)d_in[9];
    const float* w2_b  = (const float*)d_in[10];
    float* out = (float*)d_out;
    (void)in_sizes; (void)n_in; (void)out_size;

    __half *p_inh, *p_w1h, *p_w2h, *p_pwT, *p_xh, *p_yh, *p_zh;
    float *p_invnd, *p_invnp;
    cudaGetSymbolAddress((void**)&p_inh, g_inh);
    cudaGetSymbolAddress((void**)&p_w1h, g_w1h);
    cudaGetSymbolAddress((void**)&p_w2h, g_w2h);
    cudaGetSymbolAddress((void**)&p_pwT, g_pwT);
    cudaGetSymbolAddress((void**)&p_xh, g_xh);
    cudaGetSymbolAddress((void**)&p_yh, g_yh);
    cudaGetSymbolAddress((void**)&p_zh, g_zh);
    cudaGetSymbolAddress((void**)&p_invnd, g_invnd);
    cudaGetSymbolAddress((void**)&p_invnp, g_invnp);

    // fp16 conversions (contiguous, K-major already)
    {
        long long t1 = (long long)H1C * DIN / 4;
        cvt_kernel<<<(unsigned)((t1 + 255) / 256), 256>>>((const float4*)w1_w, (uint2*)p_w1h, t1);
        long long t2 = (long long)BATCH * TT * DIN / 4;
        cvt_kernel<<<(unsigned)((t2 + 255) / 256), 256>>>((const float4*)input, (uint2*)p_inh, t2);
        long long t3 = (long long)DIN * H2C / 4;
        cvt_kernel<<<(unsigned)((t3 + 255) / 256), 256>>>((const float4*)w2_w, (uint2*)p_w2h, t3);
    }
    tsplit_kernel<<<dim3(H2C / 32, H1C / 32, BATCH), dim3(32, 8)>>>(p_w, p_pwT);
    dnorm_kernel<<<BATCH * KW, 128>>>(d_w, p_invnd);
    pnorm_kernel<<<BATCH * H2C / 8, 256>>>(p_pwT, p_invnp);

    // GEMM1: x[b][t][c] = mish( sum_d input[t,d]*w1[c,d] + w1_b[c] )
    gemm_mma<1><<<dim3(H1C / 128, TT / 128, BATCH), 256>>>(
        p_inh, (long long)TT * DIN, p_w1h, 0,
        (void*)p_xh, (long long)TT * H1C, DIN, H1C,
        w1_b, 0, nullptr, 0, nullptr);

    // depthwise conv -> y (includes *T, +d_b, *p_g)
    dwconv_kernel<<<dim3(H1C / 128, TT / 64, BATCH), 256>>>(
        p_xh, p_yh, d_w, d_g, d_b, p_g, p_invnd);

    // GEMM2: z[b][t][o] = invnp[b,o]*( sum_c y[t,c]*pwT[o,c] ) + p_b[b,o]
    gemm_mma<2><<<dim3(H2C / 128, TT / 128, BATCH), 256>>>(
        p_yh, (long long)TT * H1C, p_pwT, (long long)H2C * H1C,
        (void*)p_zh, (long long)TT * H2C, H1C, H2C,
        p_invnp, H2C, p_b, H2C, nullptr);

    // GEMM3: out[b][t][d] = sum_o z[t,o]*w2[d,o] + w2_b[d] + input[b][t][d]
    gemm_mma<3><<<dim3(DIN / 128, TT / 128, BATCH), 256>>>(
        p_zh, (long long)TT * H2C, p_w2h, 0,
        (void*)out, (long long)TT * DIN, H2C, DIN,
        w2_b, 0, nullptr, 0, input);
}

// round 6
// speedup vs baseline: 4.4948x; 1.0655x over previous
#include <cuda_runtime.h>
#include <cuda_fp16.h>
#include <stdint.h>
#include <math.h>

// Problem constants
#define BATCH 16
#define TT    1024
#define DIN   384
#define H1C   1024
#define H2C   1024
#define KW    9

// ---------------- scratch (device globals) -----------------------------------
__device__ __align__(128) __half g_inh[BATCH * TT * DIN];     // fp16 input   [b][t][384]
__device__ __align__(128) __half g_w1h[H1C * DIN];            // fp16 w1      [c][384]
__device__ __align__(128) __half g_w2h[DIN * H2C];            // fp16 w2      [d][1024]
__device__ __align__(128) __half g_pwT[BATCH * H2C * H1C];    // fp16 p_w^T   [b][o][1024]
__device__ __align__(128) __half g_xh [BATCH * TT * H1C];     // mish out     [b][t][c]
__device__ __align__(128) __half g_yh [BATCH * TT * H1C];     // conv out     [b][t][c]
__device__ __align__(128) __half g_zh [BATCH * TT * H2C];     // pointwise    [b][t][o]
__device__ float g_invnd[BATCH * KW];
__device__ float g_invnp[BATCH * H2C];

// ---------------- helpers ----------------------------------------------------
__device__ __forceinline__ float mish_f(float v) {
    float sp = fmaxf(v, 0.f) + log1pf(expf(-fabsf(v)));
    return v * tanhf(sp);
}

__device__ __forceinline__ unsigned smem_u32(const void* p) {
    unsigned a;
    asm("{ .reg .u64 t; cvta.to.shared.u64 t, %1; cvt.u32.u64 %0, t; }" : "=r"(a) : "l"(p));
    return a;
}

__device__ __forceinline__ void cp_async16(unsigned dst, const void* src) {
    asm volatile("cp.async.cg.shared.global [%0], [%1], 16;" :: "r"(dst), "l"(src));
}

__device__ __forceinline__ void ldsm_x4(unsigned* r, unsigned addr) {
    asm volatile("ldmatrix.sync.aligned.m8n8.x4.shared.b16 {%0,%1,%2,%3}, [%4];"
        : "=r"(r[0]), "=r"(r[1]), "=r"(r[2]), "=r"(r[3]) : "r"(addr));
}

__device__ __forceinline__ void mma16816(float* d, const unsigned* a, unsigned b0, unsigned b1) {
    asm volatile("mma.sync.aligned.m16n8k16.row.col.f32.f16.f16.f32 "
        "{%0,%1,%2,%3}, {%4,%5,%6,%7}, {%8,%9}, {%0,%1,%2,%3};"
        : "+f"(d[0]), "+f"(d[1]), "+f"(d[2]), "+f"(d[3])
        : "r"(a[0]), "r"(a[1]), "r"(a[2]), "r"(a[3]), "r"(b0), "r"(b1));
}

// ---------------- cvt: f32 -> f16, contiguous (total % 4 == 0) ---------------
__global__ void cvt_kernel(const float4* __restrict__ in, uint2* __restrict__ out,
                           long long total4) {
    long long i = (long long)blockIdx.x * blockDim.x + threadIdx.x;
    if (i >= total4) return;
    float4 v = in[i];
    __half2 a = __floats2half2_rn(v.x, v.y);
    __half2 b = __floats2half2_rn(v.z, v.w);
    out[i] = make_uint2(*(unsigned*)&a, *(unsigned*)&b);
}

// ---------------- transpose p_w [b][c][o] -> fp16 [b][o][c] (half2 writes) ---
__global__ void tsplit_kernel(const float* __restrict__ in, __half* __restrict__ out) {
    __shared__ float tile[64][33];
    int b = blockIdx.z;
    int o0 = blockIdx.x * 32, c0 = blockIdx.y * 64;
    const float* I = in + (long long)b * H1C * H2C;
    __half* O = out + (long long)b * H2C * H1C;
    int tx = threadIdx.x, ty = threadIdx.y;  // 32 x 8
#pragma unroll
    for (int i = ty; i < 64; i += 8)
        tile[i][tx] = I[(long long)(c0 + i) * H2C + o0 + tx];
    __syncthreads();
#pragma unroll
    for (int i = ty; i < 32; i += 8) {
        __half2 v = __floats2half2_rn(tile[2 * tx][i], tile[2 * tx + 1][i]);
        *(__half2*)(O + (long long)(o0 + i) * H1C + c0 + 2 * tx) = v;
    }
}

// ---------------- d_w norm over H1 per (b,k) ---------------------------------
__global__ void dnorm_kernel(const float* __restrict__ d_w, float* __restrict__ invnd) {
    int b = blockIdx.x / KW, k = blockIdx.x % KW;
    float s = 0.f;
    for (int c = threadIdx.x; c < H1C; c += 128) {
        float v = d_w[((long long)b * H1C + c) * KW + k];
        s += v * v;
    }
#pragma unroll
    for (int o = 16; o > 0; o >>= 1) s += __shfl_xor_sync(0xffffffffu, s, o);
    __shared__ float ws[4];
    int lane = threadIdx.x & 31, wid = threadIdx.x >> 5;
    if (lane == 0) ws[wid] = s;
    __syncthreads();
    if (threadIdx.x == 0) {
        float t = ws[0] + ws[1] + ws[2] + ws[3];
        invnd[b * KW + k] = 1.f / fmaxf(sqrtf(t), 1e-12f);
    }
}

// ---------------- p_w norm over H1 per (b,o), from transposed fp16 -----------
__global__ void pnorm_kernel(const __half* __restrict__ pwT, float* __restrict__ invnp) {
    int row = blockIdx.x * 8 + (threadIdx.x >> 5);  // warp per (b,o) row
    int lane = threadIdx.x & 31;
    const __half2* p = (const __half2*)(pwT + (long long)row * H1C);
    float s = 0.f;
#pragma unroll 4
    for (int j = lane; j < H1C / 2; j += 32) {
        float2 v = __half22float2(p[j]);
        s += v.x * v.x + v.y * v.y;
    }
#pragma unroll
    for (int o = 16; o > 0; o >>= 1) s += __shfl_xor_sync(0xffffffffu, s, o);
    if (lane == 0) invnp[row] = 1.f / fmaxf(sqrtf(s), 1e-12f);
}

// ---------------- depthwise conv along t; x fp16 -> y fp16 -------------------
__global__ void dwconv_kernel(const __half* __restrict__ x, __half* __restrict__ y,
                              const float* __restrict__ d_w, const float* __restrict__ d_g,
                              const float* __restrict__ d_b, const float* __restrict__ p_g,
                              const float* __restrict__ invnd) {
    int b = blockIdx.z;
    int c0 = blockIdx.x * 128;
    int t0 = blockIdx.y * 64;
    __shared__ float xs[72][128];
    __shared__ float ws[KW][128];
    __shared__ float sdb[128], spg[128];
    int tid = threadIdx.x;  // 256
    const __half* xb = x + (long long)b * TT * H1C;
    for (int i = tid; i < 72 * 64; i += 256) {
        int r = i >> 6, c2 = i & 63;
        int t = t0 - 4 + r;
        float2 v = make_float2(0.f, 0.f);
        if (t >= 0 && t < TT)
            v = __half22float2(*(const __half2*)(xb + (long long)t * H1C + c0 + 2 * c2));
        xs[r][2 * c2] = v.x;
        xs[r][2 * c2 + 1] = v.y;
    }
    if (tid < 128) {
        int c = c0 + tid;
        float g = d_g[b * H1C + c];
#pragma unroll
        for (int k = 0; k < KW; k++)
            ws[k][tid] = d_w[((long long)b * H1C + c) * KW + k] * invnd[b * KW + k] * g;
        sdb[tid] = d_b[b * H1C + c];
        spg[tid] = p_g[b * H1C + c];
    }
    __syncthreads();
    int tx = tid & 127, ty = tid >> 7;
    float w9[KW];
#pragma unroll
    for (int k = 0; k < KW; k++) w9[k] = ws[k][tx];
    float db = sdb[tx], pg = spg[tx];
    __half* yb = y + (long long)b * TT * H1C;
#pragma unroll 4
    for (int q = 0; q < 32; q++) {
        int tt = ty * 32 + q;
        float a = 0.f;
#pragma unroll
        for (int k = 0; k < KW; k++) a = fmaf(xs[tt + k][tx], w9[k], a);
        float v = (a * (float)TT + db) * pg;
        yb[(long long)(t0 + tt) * H1C + c0 + tx] = __float2half(v);
    }
}

// ---------------- mma.sync fp16 GEMM: D[m,n] = sum_k A[m,k]*B[n,k] -----------
// 4-stage cp.async ring, one __syncthreads per chunk, prefetch distance 3.
// MODE 1: C fp16 = mish(acc + aux1[n])
// MODE 2: C fp16 = acc*aux1[b,n] + aux2[b,n]
// MODE 3: C f32 = acc + aux1[n] + R[b][m][n]
#define PITCH   80   // bytes per 32-half smem row (64B data + 16B pad)
#define NSTAGE  4
#define OPSTR   (128 * PITCH)            // 10240 per operand per stage
#define STSTR   (2 * OPSTR)              // 20480 per stage
#define SMEM_GEMM (NSTAGE * STSTR)       // 81920

template <int MODE>
__global__ void __launch_bounds__(256, 2)
gemm_mma(const __half* __restrict__ A, long long sA,
         const __half* __restrict__ B, long long sB,
         void* __restrict__ Cv, long long sC,
         int Ks, int ldc,
         const float* __restrict__ aux1, int a1s,
         const float* __restrict__ aux2, int a2s,
         const float* __restrict__ R) {
    extern __shared__ __align__(16) unsigned char dynsm[];

    const int tid = threadIdx.x;
    const int wid = tid >> 5, lane = tid & 31;
    const int wm = wid & 1, wn = wid >> 1;   // 2 x 4 warp grid
    const int b = blockIdx.z;
    const int m0 = blockIdx.y * 128, n0 = blockIdx.x * 128;

    const char* Ab = (const char*)(A + (long long)b * sA);
    const char* Bb = (const char*)(B + (long long)b * sB);
    const long long rowb = (long long)Ks * 2;   // fp16 row bytes

    // cp.async geometry: thread t loads row t/2, 32B at (t&1)*32
    const int lrow = tid >> 1;
    const int lcB = (tid & 1) * 32;
    const char* Agp = Ab + (long long)(m0 + lrow) * rowb + lcB;
    const char* Bgp = Bb + (long long)(n0 + lrow) * rowb + lcB;
    const unsigned smBase = smem_u32(dynsm);
    const unsigned AsD = smBase + (unsigned)(lrow * PITCH + lcB);
    const unsigned BsD = smBase + OPSTR + (unsigned)(lrow * PITCH + lcB);

    const int nch = Ks >> 5;

    float acc[4][4][4];
#pragma unroll
    for (int i = 0; i < 4; i++)
#pragma unroll
        for (int j = 0; j < 4; j++)
#pragma unroll
            for (int r = 0; r < 4; r++) acc[i][j][r] = 0.f;

    // ldmatrix lane offsets
    const unsigned aLane = (unsigned)((lane & 15) * PITCH + (lane >> 4) * 16);
    const unsigned bLane = (unsigned)(((lane & 8) + (lane & 7)) * PITCH + (lane >> 4) * 16);
    const unsigned baseA0 = smBase + (unsigned)(wm * 64 * PITCH);
    const unsigned baseB0 = smBase + OPSTR + (unsigned)(wn * 32 * PITCH);

#define ISSUE(ic) do { \
    int _o = (ic) * 64; \
    unsigned _st = (unsigned)((ic) % NSTAGE) * STSTR; \
    cp_async16(AsD + _st, Agp + _o); \
    cp_async16(AsD + _st + 16, Agp + _o + 16); \
    cp_async16(BsD + _st, Bgp + _o); \
    cp_async16(BsD + _st + 16, Bgp + _o + 16); \
    asm volatile("cp.async.commit_group;"); \
} while (0)

    // prologue: NSTAGE-1 groups always committed (empty when past end)
#pragma unroll
    for (int p = 0; p < NSTAGE - 1; p++) {
        if (p < nch) ISSUE(p);
        else asm volatile("cp.async.commit_group;");
    }

    for (int ic = 0; ic < nch; ic++) {
        asm volatile("cp.async.wait_group %0;" :: "n"(NSTAGE - 2));
        __syncthreads();
        // prefetch chunk ic+3 into the slot last read at iteration ic-1
        if (ic + NSTAGE - 1 < nch) ISSUE(ic + NSTAGE - 1);
        else asm volatile("cp.async.commit_group;");

        unsigned st = (unsigned)(ic % NSTAGE) * STSTR;
        unsigned bA = baseA0 + st, bB = baseB0 + st;
#pragma unroll
        for (int ks = 0; ks < 2; ks++) {
            unsigned afr[4][4];
#pragma unroll
            for (int mi = 0; mi < 4; mi++)
                ldsm_x4(afr[mi], bA + (unsigned)(mi * 16 * PITCH) + (unsigned)(ks * 32) + aLane);
            unsigned bfr[4][2];
#pragma unroll
            for (int nj = 0; nj < 2; nj++) {
                unsigned r[4];
                ldsm_x4(r, bB + (unsigned)(nj * 16 * PITCH) + (unsigned)(ks * 32) + bLane);
                bfr[2 * nj][0] = r[0]; bfr[2 * nj][1] = r[2];
                bfr[2 * nj + 1][0] = r[1]; bfr[2 * nj + 1][1] = r[3];
            }
#pragma unroll
            for (int mi = 0; mi < 4; mi++)
#pragma unroll
                for (int ni = 0; ni < 4; ni++)
                    mma16816(acc[mi][ni], afr[mi], bfr[ni][0], bfr[ni][1]);
        }
    }
#undef ISSUE

    // epilogue: rows quad, quad+8; cols 2*(lane&3)+{0,1}
    const int quad = lane >> 2;
    const int col2 = (lane & 3) * 2;
#pragma unroll
    for (int mi = 0; mi < 4; mi++) {
#pragma unroll
        for (int half = 0; half < 2; half++) {
            int m = m0 + wm * 64 + mi * 16 + quad + half * 8;
#pragma unroll
            for (int ni = 0; ni < 4; ni++) {
                int n = n0 + wn * 32 + ni * 8 + col2;
                float v0 = acc[mi][ni][2 * half];
                float v1 = acc[mi][ni][2 * half + 1];
                if (MODE == 1) {
                    v0 = mish_f(v0 + aux1[n]);
                    v1 = mish_f(v1 + aux1[n + 1]);
                    __half* C = (__half*)Cv + (long long)b * sC + (long long)m * ldc + n;
                    *(__half2*)C = __floats2half2_rn(v0, v1);
                } else if (MODE == 2) {
                    v0 = v0 * aux1[b * a1s + n] + aux2[b * a2s + n];
                    v1 = v1 * aux1[b * a1s + n + 1] + aux2[b * a2s + n + 1];
                    __half* C = (__half*)Cv + (long long)b * sC + (long long)m * ldc + n;
                    *(__half2*)C = __floats2half2_rn(v0, v1);
                } else {
                    long long off = (long long)b * sC + (long long)m * ldc + n;
                    v0 = v0 + aux1[n] + R[off];
                    v1 = v1 + aux1[n + 1] + R[off + 1];
                    *(float2*)((float*)Cv + off) = make_float2(v0, v1);
                }
            }
        }
    }
}

// ---------------- launch ------------------------------------------------------
extern "C" void kernel_launch(void* const* d_in, const int* in_sizes, int n_in,
                              void* d_out, int out_size) {
    const float* input = (const float*)d_in[0];
    const float* d_w   = (const float*)d_in[1];
    const float* d_g   = (const float*)d_in[2];
    const float* d_b   = (const float*)d_in[3];
    const float* p_w   = (const float*)d_in[4];
    const float* p_g   = (const float*)d_in[5];
    const float* p_b   = (const float*)d_in[6];
    const float* w1_w  = (const float*)d_in[7];
    const float* w1_b  = (const float*)d_in[8];
    const float* w2_w  = (const float*)d_in[9];
    const float* w2_b  = (const float*)d_in[10];
    float* out = (float*)d_out;
    (void)in_sizes; (void)n_in; (void)out_size;

    __half *p_inh, *p_w1h, *p_w2h, *p_pwT, *p_xh, *p_yh, *p_zh;
    float *p_invnd, *p_invnp;
    cudaGetSymbolAddress((void**)&p_inh, g_inh);
    cudaGetSymbolAddress((void**)&p_w1h, g_w1h);
    cudaGetSymbolAddress((void**)&p_w2h, g_w2h);
    cudaGetSymbolAddress((void**)&p_pwT, g_pwT);
    cudaGetSymbolAddress((void**)&p_xh, g_xh);
    cudaGetSymbolAddress((void**)&p_yh, g_yh);
    cudaGetSymbolAddress((void**)&p_zh, g_zh);
    cudaGetSymbolAddress((void**)&p_invnd, g_invnd);
    cudaGetSymbolAddress((void**)&p_invnp, g_invnp);

    // opt-in to 80KB dynamic smem for the GEMM instantiations (idempotent)
    cudaFuncSetAttribute(gemm_mma<1>, cudaFuncAttributeMaxDynamicSharedMemorySize, SMEM_GEMM);
    cudaFuncSetAttribute(gemm_mma<2>, cudaFuncAttributeMaxDynamicSharedMemorySize, SMEM_GEMM);
    cudaFuncSetAttribute(gemm_mma<3>, cudaFuncAttributeMaxDynamicSharedMemorySize, SMEM_GEMM);

    // fp16 conversions (contiguous, K-major already)
    {
        long long t1 = (long long)H1C * DIN / 4;
        cvt_kernel<<<(unsigned)((t1 + 255) / 256), 256>>>((const float4*)w1_w, (uint2*)p_w1h, t1);
        long long t2 = (long long)BATCH * TT * DIN / 4;
        cvt_kernel<<<(unsigned)((t2 + 255) / 256), 256>>>((const float4*)input, (uint2*)p_inh, t2);
        long long t3 = (long long)DIN * H2C / 4;
        cvt_kernel<<<(unsigned)((t3 + 255) / 256), 256>>>((const float4*)w2_w, (uint2*)p_w2h, t3);
    }
    tsplit_kernel<<<dim3(H2C / 32, H1C / 64, BATCH), dim3(32, 8)>>>(p_w, p_pwT);
    dnorm_kernel<<<BATCH * KW, 128>>>(d_w, p_invnd);
    pnorm_kernel<<<BATCH * H2C / 8, 256>>>(p_pwT, p_invnp);

    // GEMM1: x[b][t][c] = mish( sum_d input[t,d]*w1[c,d] + w1_b[c] )
    gemm_mma<1><<<dim3(H1C / 128, TT / 128, BATCH), 256, SMEM_GEMM>>>(
        p_inh, (long long)TT * DIN, p_w1h, 0,
        (void*)p_xh, (long long)TT * H1C, DIN, H1C,
        w1_b, 0, nullptr, 0, nullptr);

    // depthwise conv -> y (includes *T, +d_b, *p_g)
    dwconv_kernel<<<dim3(H1C / 128, TT / 64, BATCH), 256>>>(
        p_xh, p_yh, d_w, d_g, d_b, p_g, p_invnd);

    // GEMM2: z[b][t][o] = invnp[b,o]*( sum_c y[t,c]*pwT[o,c] ) + p_b[b,o]
    gemm_mma<2><<<dim3(H2C / 128, TT / 128, BATCH), 256, SMEM_GEMM>>>(
        p_yh, (long long)TT * H1C, p_pwT, (long long)H2C * H1C,
        (void*)p_zh, (long long)TT * H2C, H1C, H2C,
        p_invnp, H2C, p_b, H2C, nullptr);

    // GEMM3: out[b][t][d] = sum_o z[t,o]*w2[d,o] + w2_b[d] + input[b][t][d]
    gemm_mma<3><<<dim3(DIN / 128, TT / 128, BATCH), 256, SMEM_GEMM>>>(
        p_zh, (long long)TT * H2C, p_w2h, 0,
        (void*)out, (long long)TT * DIN, H2C, DIN,
        w2_b, 0, nullptr, 0, input);
}

// round 7
// speedup vs baseline: 4.6601x; 1.0368x over previous
#include <cuda_runtime.h>
#include <cuda_fp16.h>
#include <stdint.h>
#include <math.h>

// Problem constants
#define BATCH 16
#define TT    1024
#define DIN   384
#define H1C   1024
#define H2C   1024
#define KW    9

// ---------------- scratch (device globals) -----------------------------------
__device__ __align__(128) __half g_inh[BATCH * TT * DIN];     // fp16 input   [b][t][384]
__device__ __align__(128) __half g_w1h[H1C * DIN];            // fp16 w1      [c][384]
__device__ __align__(128) __half g_w2h[DIN * H2C];            // fp16 w2      [d][1024]
__device__ __align__(128) __half g_pwT[BATCH * H2C * H1C];    // fp16 p_w^T   [b][o][1024]
__device__ __align__(128) __half g_xh [BATCH * TT * H1C];     // mish out     [b][t][c]
__device__ __align__(128) __half g_yh [BATCH * TT * H1C];     // conv out     [b][t][c]
__device__ __align__(128) __half g_zh [BATCH * TT * H2C];     // pointwise    [b][t][o]
__device__ float g_invnd[BATCH * KW];
__device__ float g_invnp[BATCH * H2C];

// ---------------- helpers ----------------------------------------------------
__device__ __forceinline__ float mish_f(float v) {
    float sp = fmaxf(v, 0.f) + log1pf(expf(-fabsf(v)));
    return v * tanhf(sp);
}

__device__ __forceinline__ unsigned smem_u32(const void* p) {
    unsigned a;
    asm("{ .reg .u64 t; cvta.to.shared.u64 t, %1; cvt.u32.u64 %0, t; }" : "=r"(a) : "l"(p));
    return a;
}

__device__ __forceinline__ void cp_async16(unsigned dst, const void* src) {
    asm volatile("cp.async.cg.shared.global [%0], [%1], 16;" :: "r"(dst), "l"(src));
}

__device__ __forceinline__ void ldsm_x4(unsigned* r, unsigned addr) {
    asm volatile("ldmatrix.sync.aligned.m8n8.x4.shared.b16 {%0,%1,%2,%3}, [%4];"
        : "=r"(r[0]), "=r"(r[1]), "=r"(r[2]), "=r"(r[3]) : "r"(addr));
}

__device__ __forceinline__ void mma16816(float* d, const unsigned* a, unsigned b0, unsigned b1) {
    asm volatile("mma.sync.aligned.m16n8k16.row.col.f32.f16.f16.f32 "
        "{%0,%1,%2,%3}, {%4,%5,%6,%7}, {%8,%9}, {%0,%1,%2,%3};"
        : "+f"(d[0]), "+f"(d[1]), "+f"(d[2]), "+f"(d[3])
        : "r"(a[0]), "r"(a[1]), "r"(a[2]), "r"(a[3]), "r"(b0), "r"(b1));
}

// ---------------- mma.sync fp16 GEMM body: D[m,n] = sum_k A[m,k]*B[n,k] ------
// 4-stage cp.async ring, one __syncthreads per chunk, prefetch distance 3.
// MODE 1: C fp16 = mish(acc + aux1[n])
// MODE 2: C fp16 = acc*aux1[b,n] + aux2[b,n]
// MODE 3: C f32 = acc + aux1[n] + R[b][m][n]
#define PITCH   80   // bytes per 32-half smem row (64B data + 16B pad)
#define NSTAGE  4
#define OPSTR   (128 * PITCH)            // 10240 per operand per stage
#define STSTR   (2 * OPSTR)              // 20480 per stage
#define SMEM_GEMM (NSTAGE * STSTR)       // 81920

template <int MODE>
__device__ __forceinline__ void gemm_body(
    int m0, int n0, int b,
    const __half* __restrict__ A, long long sA,
    const __half* __restrict__ B, long long sB,
    void* __restrict__ Cv, long long sC,
    int Ks, int ldc,
    const float* __restrict__ aux1, int a1s,
    const float* __restrict__ aux2, int a2s,
    const float* __restrict__ R,
    unsigned char* dynsm) {
    const int tid = threadIdx.x;
    const int wid = tid >> 5, lane = tid & 31;
    const int wm = wid & 1, wn = wid >> 1;   // 2 x 4 warp grid

    const char* Ab = (const char*)(A + (long long)b * sA);
    const char* Bb = (const char*)(B + (long long)b * sB);
    const long long rowb = (long long)Ks * 2;   // fp16 row bytes

    // cp.async geometry: thread t loads row t/2, 32B at (t&1)*32
    const int lrow = tid >> 1;
    const int lcB = (tid & 1) * 32;
    const char* Agp = Ab + (long long)(m0 + lrow) * rowb + lcB;
    const char* Bgp = Bb + (long long)(n0 + lrow) * rowb + lcB;
    const unsigned smBase = smem_u32(dynsm);
    const unsigned AsD = smBase + (unsigned)(lrow * PITCH + lcB);
    const unsigned BsD = smBase + OPSTR + (unsigned)(lrow * PITCH + lcB);

    const int nch = Ks >> 5;

    float acc[4][4][4];
#pragma unroll
    for (int i = 0; i < 4; i++)
#pragma unroll
        for (int j = 0; j < 4; j++)
#pragma unroll
            for (int r = 0; r < 4; r++) acc[i][j][r] = 0.f;

    // ldmatrix lane offsets
    const unsigned aLane = (unsigned)((lane & 15) * PITCH + (lane >> 4) * 16);
    const unsigned bLane = (unsigned)(((lane & 8) + (lane & 7)) * PITCH + (lane >> 4) * 16);
    const unsigned baseA0 = smBase + (unsigned)(wm * 64 * PITCH);
    const unsigned baseB0 = smBase + OPSTR + (unsigned)(wn * 32 * PITCH);

#define ISSUE(ic) do { \
    int _o = (ic) * 64; \
    unsigned _st = (unsigned)((ic) % NSTAGE) * STSTR; \
    cp_async16(AsD + _st, Agp + _o); \
    cp_async16(AsD + _st + 16, Agp + _o + 16); \
    cp_async16(BsD + _st, Bgp + _o); \
    cp_async16(BsD + _st + 16, Bgp + _o + 16); \
    asm volatile("cp.async.commit_group;"); \
} while (0)

    // prologue: NSTAGE-1 groups always committed (empty when past end)
#pragma unroll
    for (int p = 0; p < NSTAGE - 1; p++) {
        if (p < nch) ISSUE(p);
        else asm volatile("cp.async.commit_group;");
    }

    for (int ic = 0; ic < nch; ic++) {
        asm volatile("cp.async.wait_group %0;" :: "n"(NSTAGE - 2));
        __syncthreads();
        // prefetch chunk ic+3 into the slot last read at iteration ic-1
        if (ic + NSTAGE - 1 < nch) ISSUE(ic + NSTAGE - 1);
        else asm volatile("cp.async.commit_group;");

        unsigned st = (unsigned)(ic % NSTAGE) * STSTR;
        unsigned bA = baseA0 + st, bB = baseB0 + st;
#pragma unroll
        for (int ks = 0; ks < 2; ks++) {
            unsigned afr[4][4];
#pragma unroll
            for (int mi = 0; mi < 4; mi++)
                ldsm_x4(afr[mi], bA + (unsigned)(mi * 16 * PITCH) + (unsigned)(ks * 32) + aLane);
            unsigned bfr[4][2];
#pragma unroll
            for (int nj = 0; nj < 2; nj++) {
                unsigned r[4];
                ldsm_x4(r, bB + (unsigned)(nj * 16 * PITCH) + (unsigned)(ks * 32) + bLane);
                bfr[2 * nj][0] = r[0]; bfr[2 * nj][1] = r[2];
                bfr[2 * nj + 1][0] = r[1]; bfr[2 * nj + 1][1] = r[3];
            }
#pragma unroll
            for (int mi = 0; mi < 4; mi++)
#pragma unroll
                for (int ni = 0; ni < 4; ni++)
                    mma16816(acc[mi][ni], afr[mi], bfr[ni][0], bfr[ni][1]);
        }
    }
#undef ISSUE

    // epilogue: rows quad, quad+8; cols 2*(lane&3)+{0,1}
    const int quad = lane >> 2;
    const int col2 = (lane & 3) * 2;
#pragma unroll
    for (int mi = 0; mi < 4; mi++) {
#pragma unroll
        for (int half = 0; half < 2; half++) {
            int m = m0 + wm * 64 + mi * 16 + quad + half * 8;
#pragma unroll
            for (int ni = 0; ni < 4; ni++) {
                int n = n0 + wn * 32 + ni * 8 + col2;
                float v0 = acc[mi][ni][2 * half];
                float v1 = acc[mi][ni][2 * half + 1];
                if (MODE == 1) {
                    v0 = mish_f(v0 + aux1[n]);
                    v1 = mish_f(v1 + aux1[n + 1]);
                    __half* C = (__half*)Cv + (long long)b * sC + (long long)m * ldc + n;
                    *(__half2*)C = __floats2half2_rn(v0, v1);
                } else if (MODE == 2) {
                    v0 = v0 * aux1[b * a1s + n] + aux2[b * a2s + n];
                    v1 = v1 * aux1[b * a1s + n + 1] + aux2[b * a2s + n + 1];
                    __half* C = (__half*)Cv + (long long)b * sC + (long long)m * ldc + n;
                    *(__half2*)C = __floats2half2_rn(v0, v1);
                } else {
                    long long off = (long long)b * sC + (long long)m * ldc + n;
                    v0 = v0 + aux1[n] + R[off];
                    v1 = v1 + aux1[n + 1] + R[off + 1];
                    *(float2*)((float*)Cv + off) = make_float2(v0, v1);
                }
            }
        }
    }
}

// ---------------- standalone GEMM kernel (3D grid) ---------------------------
template <int MODE>
__global__ void __launch_bounds__(256, 2)
gemm_mma(const __half* __restrict__ A, long long sA,
         const __half* __restrict__ B, long long sB,
         void* __restrict__ Cv, long long sC,
         int Ks, int ldc,
         const float* __restrict__ aux1, int a1s,
         const float* __restrict__ aux2, int a2s,
         const float* __restrict__ R) {
    extern __shared__ __align__(16) unsigned char dynsm[];
    gemm_body<MODE>(blockIdx.y * 128, blockIdx.x * 128, blockIdx.z,
                    A, sA, B, sB, Cv, sC, Ks, ldc, aux1, a1s, aux2, a2s, R, dynsm);
}

// ---------------- prep: cvt input/w1/w2 + dnorm, one launch ------------------
// blocks: [0,6144) input cvt | [6144,6528) w1 | [6528,6912) w2 | [6912,6930) dnorm
__global__ void prep_kernel(const float* __restrict__ input, const float* __restrict__ w1_w,
                            const float* __restrict__ w2_w, const float* __restrict__ d_w,
                            __half* __restrict__ inh, __half* __restrict__ w1h,
                            __half* __restrict__ w2h, float* __restrict__ invnd) {
    int bx = blockIdx.x;
    int tid = threadIdx.x;
    if (bx < 6912) {
        const float4* src;
        uint2* dst;
        long long i;
        if (bx < 6144) {
            src = (const float4*)input; dst = (uint2*)inh;
            i = (long long)bx * 256 + tid;
        } else if (bx < 6528) {
            src = (const float4*)w1_w; dst = (uint2*)w1h;
            i = (long long)(bx - 6144) * 256 + tid;
        } else {
            src = (const float4*)w2_w; dst = (uint2*)w2h;
            i = (long long)(bx - 6528) * 256 + tid;
        }
        float4 v = src[i];
        __half2 a = __floats2half2_rn(v.x, v.y);
        __half2 b = __floats2half2_rn(v.z, v.w);
        dst[i] = make_uint2(*(unsigned*)&a, *(unsigned*)&b);
    } else {
        // dnorm: warp per (b,k), 18 blocks x 8 warps = 144
        int w = (bx - 6912) * 8 + (tid >> 5);
        int lane = tid & 31;
        int b = w / KW, k = w - KW * b;
        float s = 0.f;
#pragma unroll 8
        for (int c = lane; c < H1C; c += 32) {
            float v = d_w[((long long)b * H1C + c) * KW + k];
            s += v * v;
        }
#pragma unroll
        for (int o = 16; o > 0; o >>= 1) s += __shfl_xor_sync(0xffffffffu, s, o);
        if (lane == 0) invnd[b * KW + k] = 1.f / fmaxf(sqrtf(s), 1e-12f);
    }
}

// ---------------- fused GEMM1 + p_w transpose --------------------------------
// blocks [0,1024): GEMM1 tiles | [1024,5120): tsplit 64x64 tiles
__global__ void __launch_bounds__(256, 2)
gemm1_tsplit(const __half* __restrict__ A, const __half* __restrict__ Bw,
             __half* __restrict__ X, const float* __restrict__ w1b,
             const float* __restrict__ pw, __half* __restrict__ pwT) {
    extern __shared__ __align__(16) unsigned char dynsm[];
    int bx = blockIdx.x;
    int tid = threadIdx.x;
    if (bx < 1024) {
        int b = bx >> 6;
        int rem = bx & 63;
        int m0 = (rem >> 3) * 128, n0 = (rem & 7) * 128;
        gemm_body<1>(m0, n0, b, A, (long long)TT * DIN, Bw, 0,
                     (void*)X, (long long)TT * H1C, DIN, H1C,
                     w1b, 0, nullptr, 0, nullptr, dynsm);
    } else {
        // tsplit: [b][c][o] f32 -> [b][o][c] fp16, 64x64 tiles
        int lin = bx - 1024;
        int b = lin >> 8;
        int rem = lin & 255;
        int c0 = (rem >> 4) * 64;
        int o0 = (rem & 15) * 64;
        float(*tile)[65] = (float(*)[65])dynsm;
        const float* I = pw + (long long)b * H1C * H2C;
        __half* O = pwT + (long long)b * H2C * H1C;
        int tx = tid & 15, ty = tid >> 4;  // 16 x 16
#pragma unroll
        for (int it = 0; it < 4; it++) {
            int r = ty + it * 16;
            float4 v = *(const float4*)(I + (long long)(c0 + r) * H2C + o0 + tx * 4);
            tile[r][tx * 4] = v.x;
            tile[r][tx * 4 + 1] = v.y;
            tile[r][tx * 4 + 2] = v.z;
            tile[r][tx * 4 + 3] = v.w;
        }
        __syncthreads();
        int wid = tid >> 5, lane = tid & 31;
#pragma unroll
        for (int o = wid; o < 64; o += 8) {
            __half2 v = __floats2half2_rn(tile[2 * lane][o], tile[2 * lane + 1][o]);
            *(__half2*)(O + (long long)(o0 + o) * H1C + c0 + 2 * lane) = v;
        }
    }
}

// ---------------- fused depthwise conv + pnorm -------------------------------
// blocks [0,2048): dwconv | [2048,4096): pnorm (warp per (b,o) row)
__global__ void dwconv_pnorm(const __half* __restrict__ x, __half* __restrict__ y,
                             const float* __restrict__ d_w, const float* __restrict__ d_g,
                             const float* __restrict__ d_b, const float* __restrict__ p_g,
                             const float* __restrict__ invnd,
                             const __half* __restrict__ pwT, float* __restrict__ invnp) {
    int bx = blockIdx.x;
    int tid = threadIdx.x;  // 256
    if (bx < 2048) {
        int b = bx >> 7;
        int rem = bx & 127;
        int c0 = (rem & 7) * 128;
        int t0 = (rem >> 3) * 64;
        __shared__ float xs[72][128];
        __shared__ float ws[KW][128];
        __shared__ float sdb[128], spg[128];
        const __half* xb = x + (long long)b * TT * H1C;
        for (int i = tid; i < 72 * 64; i += 256) {
            int r = i >> 6, c2 = i & 63;
            int t = t0 - 4 + r;
            float2 v = make_float2(0.f, 0.f);
            if (t >= 0 && t < TT)
                v = __half22float2(*(const __half2*)(xb + (long long)t * H1C + c0 + 2 * c2));
            xs[r][2 * c2] = v.x;
            xs[r][2 * c2 + 1] = v.y;
        }
        if (tid < 128) {
            int c = c0 + tid;
            float g = d_g[b * H1C + c];
#pragma unroll
            for (int k = 0; k < KW; k++)
                ws[k][tid] = d_w[((long long)b * H1C + c) * KW + k] * invnd[b * KW + k] * g;
            sdb[tid] = d_b[b * H1C + c];
            spg[tid] = p_g[b * H1C + c];
        }
        __syncthreads();
        int tx = tid & 127, ty = tid >> 7;
        float w9[KW];
#pragma unroll
        for (int k = 0; k < KW; k++) w9[k] = ws[k][tx];
        float db = sdb[tx], pg = spg[tx];
        __half* yb = y + (long long)b * TT * H1C;
#pragma unroll 4
        for (int q = 0; q < 32; q++) {
            int tt = ty * 32 + q;
            float a = 0.f;
#pragma unroll
            for (int k = 0; k < KW; k++) a = fmaf(xs[tt + k][tx], w9[k], a);
            float v = (a * (float)TT + db) * pg;
            yb[(long long)(t0 + tt) * H1C + c0 + tx] = __float2half(v);
        }
    } else {
        int row = (bx - 2048) * 8 + (tid >> 5);
        int lane = tid & 31;
        const __half2* p = (const __half2*)(pwT + (long long)row * H1C);
        float s = 0.f;
#pragma unroll 4
        for (int j = lane; j < H1C / 2; j += 32) {
            float2 v = __half22float2(p[j]);
            s += v.x * v.x + v.y * v.y;
        }
#pragma unroll
        for (int o = 16; o > 0; o >>= 1) s += __shfl_xor_sync(0xffffffffu, s, o);
        if (lane == 0) invnp[row] = 1.f / fmaxf(sqrtf(s), 1e-12f);
    }
}

// ---------------- launch ------------------------------------------------------
extern "C" void kernel_launch(void* const* d_in, const int* in_sizes, int n_in,
                              void* d_out, int out_size) {
    const float* input = (const float*)d_in[0];
    const float* d_w   = (const float*)d_in[1];
    const float* d_g   = (const float*)d_in[2];
    const float* d_b   = (const float*)d_in[3];
    const float* p_w   = (const float*)d_in[4];
    const float* p_g   = (const float*)d_in[5];
    const float* p_b   = (const float*)d_in[6];
    const float* w1_w  = (const float*)d_in[7];
    const float* w1_b  = (const float*)d_in[8];
    const float* w2_w  = (const float*)d_in[9];
    const float* w2_b  = (const float*)d_in[10];
    float* out = (float*)d_out;
    (void)in_sizes; (void)n_in; (void)out_size;

    __half *p_inh, *p_w1h, *p_w2h, *p_pwT, *p_xh, *p_yh, *p_zh;
    float *p_invnd, *p_invnp;
    cudaGetSymbolAddress((void**)&p_inh, g_inh);
    cudaGetSymbolAddress((void**)&p_w1h, g_w1h);
    cudaGetSymbolAddress((void**)&p_w2h, g_w2h);
    cudaGetSymbolAddress((void**)&p_pwT, g_pwT);
    cudaGetSymbolAddress((void**)&p_xh, g_xh);
    cudaGetSymbolAddress((void**)&p_yh, g_yh);
    cudaGetSymbolAddress((void**)&p_zh, g_zh);
    cudaGetSymbolAddress((void**)&p_invnd, g_invnd);
    cudaGetSymbolAddress((void**)&p_invnp, g_invnp);

    // opt-in to 80KB dynamic smem (idempotent)
    cudaFuncSetAttribute(gemm1_tsplit, cudaFuncAttributeMaxDynamicSharedMemorySize, SMEM_GEMM);
    cudaFuncSetAttribute(gemm_mma<2>, cudaFuncAttributeMaxDynamicSharedMemorySize, SMEM_GEMM);
    cudaFuncSetAttribute(gemm_mma<3>, cudaFuncAttributeMaxDynamicSharedMemorySize, SMEM_GEMM);

    // 1) prep: all fp16 conversions + dnorm
    prep_kernel<<<6930, 256>>>(input, w1_w, w2_w, d_w, p_inh, p_w1h, p_w2h, p_invnd);

    // 2) GEMM1 (mish) fused with p_w transpose
    gemm1_tsplit<<<1024 + 4096, 256, SMEM_GEMM>>>(p_inh, p_w1h, p_xh, w1_b, p_w, p_pwT);

    // 3) depthwise conv (+*T, +d_b, *p_g) fused with pnorm
    dwconv_pnorm<<<4096, 256>>>(p_xh, p_yh, d_w, d_g, d_b, p_g, p_invnd, p_pwT, p_invnp);

    // 4) GEMM2: z[b][t][o] = invnp[b,o]*( sum_c y[t,c]*pwT[o,c] ) + p_b[b,o]
    gemm_mma<2><<<dim3(H2C / 128, TT / 128, BATCH), 256, SMEM_GEMM>>>(
        p_yh, (long long)TT * H1C, p_pwT, (long long)H2C * H1C,
        (void*)p_zh, (long long)TT * H2C, H1C, H2C,
        p_invnp, H2C, p_b, H2C, nullptr);

    // 5) GEMM3: out[b][t][d] = sum_o z[t,o]*w2[d,o] + w2_b[d] + input[b][t][d]
    gemm_mma<3><<<dim3(DIN / 128, TT / 128, BATCH), 256, SMEM_GEMM>>>(
        p_zh, (long long)TT * H2C, p_w2h, 0,
        (void*)out, (long long)TT * DIN, H2C, DIN,
        w2_b, 0, nullptr, 0, input);
}